// round 10
// baseline (speedup 1.0000x reference)
#include <cuda_runtime.h>
#include <math.h>

#define S 2048
#define B 2
#define D 256
#define H 8
#define DK 32
#define NBH 16
#define SPLIT 4
#define PVSPLIT 4
// fold log2(e)/sqrt(DK) into Q at projection time; then exp(s) == exp2(acc)
#define QSCALE (1.4426950408889634f * 0.17677669529663687f)

typedef unsigned long long ull;

__device__ float g_qh[NBH * S * DK];        // [bh, s, dk]
__device__ float g_kh[NBH * S * DK];
__device__ float g_vh[NBH * S * DK];
__device__ float g_qhT[NBH * DK * S];       // [bh, dk, s]
__device__ float g_khT[NBH * DK * S];
__device__ float g_vhT[NBH * DK * S];
__device__ float g_bias[(size_t)H * S * S]; // [h, q, k]
__device__ float g_rsum[SPLIT * NBH * S];   // partial rowsums from qk_sum
__device__ float g_part[PVSPLIT * NBH * S * DK]; // pv split-k partials
__device__ float g_ctx[S * B * D];          // [m = s*B+b, d]
__device__ float g_fc[S * B * D];           // fc output + residual

__device__ __forceinline__ float fast_exp2(float x) {
    float r;
    asm("ex2.approx.f32 %0, %1;" : "=f"(r) : "f"(x));
    return r;
}
// packed fp32x2 FMA (Blackwell): d = a*b + c lanewise, rn rounding (== fmaf)
__device__ __forceinline__ ull ffma2(ull a, ull b, ull c) {
    ull d;
    asm("fma.rn.f32x2 %0, %1, %2, %3;" : "=l"(d) : "l"(a), "l"(b), "l"(c));
    return d;
}
__device__ __forceinline__ ull pack2(float x, float y) {
    ull r;
    asm("mov.b64 %0, {%1, %2};" : "=l"(r) : "f"(x), "f"(y));
    return r;
}
__device__ __forceinline__ float2 unpack2(ull v) {
    float2 r;
    asm("mov.b64 {%0, %1}, %2;" : "=f"(r.x), "=f"(r.y) : "l"(v));
    return r;
}

// ---------------------------------------------------------------------------
// Kernel 1: QKV projections. 64x64 tile SGEMM, 256 threads, 4x4 micro-tile.
// ---------------------------------------------------------------------------
__global__ void proj_kernel(const float* __restrict__ q, const float* __restrict__ k,
                            const float* __restrict__ v,
                            const float* __restrict__ wq, const float* __restrict__ wk,
                            const float* __restrict__ wv) {
    __shared__ float asT[16][68];  // [k][m]
    __shared__ float bs[16][68];   // [k][n]
    int which = blockIdx.z;
    const float* x = (which == 0) ? q : (which == 1 ? k : v);
    const float* w = (which == 0) ? wq : (which == 1 ? wk : wv);
    float* out = (which == 0) ? g_qh : (which == 1 ? g_kh : g_vh);

    int m0 = blockIdx.x * 64, n0 = blockIdx.y * 64;
    int t = threadIdx.x;
    int tx = t & 15, ty = t >> 4;
    int lrowA = t >> 2, lkA = (t & 3) * 4;
    int lkB = t >> 4, lnB = (t & 15) * 4;

    ull acc2[4][2];
    #pragma unroll
    for (int i = 0; i < 4; i++) { acc2[i][0] = 0ull; acc2[i][1] = 0ull; }

    for (int k0 = 0; k0 < D; k0 += 16) {
        float4 a4 = *(const float4*)&x[(size_t)(m0 + lrowA) * D + k0 + lkA];
        float4 b4 = *(const float4*)&w[(size_t)(k0 + lkB) * D + n0 + lnB];
        asT[lkA + 0][lrowA] = a4.x; asT[lkA + 1][lrowA] = a4.y;
        asT[lkA + 2][lrowA] = a4.z; asT[lkA + 3][lrowA] = a4.w;
        *(float4*)&bs[lkB][lnB] = b4;
        __syncthreads();
        #pragma unroll
        for (int kk = 0; kk < 16; kk++) {
            float4 av = *(const float4*)&asT[kk][ty * 4];
            const ull* bp = (const ull*)&bs[kk][tx * 4];
            ull b0 = bp[0], b1 = bp[1];
            ull a2[4] = {pack2(av.x, av.x), pack2(av.y, av.y),
                         pack2(av.z, av.z), pack2(av.w, av.w)};
            #pragma unroll
            for (int i = 0; i < 4; i++) {
                acc2[i][0] = ffma2(a2[i], b0, acc2[i][0]);
                acc2[i][1] = ffma2(a2[i], b1, acc2[i][1]);
            }
        }
        __syncthreads();
    }
    float sc = (which == 0) ? QSCALE : 1.0f;
    int n = n0 + tx * 4;
    int h = n >> 5, dk = n & 31;
    #pragma unroll
    for (int qi = 0; qi < 4; qi++) {
        int m = m0 + ty * 4 + qi;
        int b = m & 1, s = m >> 1;
        float2 lo = unpack2(acc2[qi][0]);
        float2 hi = unpack2(acc2[qi][1]);
        float4 o = make_float4(lo.x * sc, lo.y * sc, hi.x * sc, hi.y * sc);
        *(float4*)&out[((size_t)(b * H + h) * S + s) * DK + dk] = o;
    }
}

// ---------------------------------------------------------------------------
// Kernel 1b: transpose heads [bh, s, dk] -> [bh, dk, s] for Q, K, V.
// ---------------------------------------------------------------------------
__global__ void head_transpose_kernel() {
    __shared__ float ts[64][33];
    int z = blockIdx.z;
    const float* src = (z == 0) ? g_qh : (z == 1 ? g_kh : g_vh);
    float* dst = (z == 0) ? g_qhT : (z == 1 ? g_khT : g_vhT);
    int bh = blockIdx.y;
    int s0 = blockIdx.x * 64;
    int t = threadIdx.x;

    for (int i = t; i < 512; i += 128) {
        int r = i >> 3, d4 = (i & 7) * 4;
        float4 a = *(const float4*)&src[((size_t)bh * S + s0 + r) * DK + d4];
        ts[r][d4 + 0] = a.x; ts[r][d4 + 1] = a.y;
        ts[r][d4 + 2] = a.z; ts[r][d4 + 3] = a.w;
    }
    __syncthreads();

    int d = t >> 2, c = t & 3;
    #pragma unroll
    for (int iter = 0; iter < 4; iter++) {
        int sl = c * 4 + iter * 16;
        float4 o = make_float4(ts[sl + 0][d], ts[sl + 1][d], ts[sl + 2][d], ts[sl + 3][d]);
        *(float4*)&dst[((size_t)bh * DK + d) * S + s0 + sl] = o;
    }
}

// ---------------------------------------------------------------------------
// Kernel 2: transpose graph_pos [k,q,h] -> g_bias [h,q,k].
// ---------------------------------------------------------------------------
__global__ void bias_transpose_kernel(const float* __restrict__ gp) {
    int qrow = blockIdx.y;
    int kk = blockIdx.x * 256 + threadIdx.x;
    const float4* p = reinterpret_cast<const float4*>(gp + ((size_t)kk * S + qrow) * H);
    float4 a = p[0];
    float4 b4 = p[1];
    float vals[8] = {a.x, a.y, a.z, a.w, b4.x, b4.y, b4.z, b4.w};
    #pragma unroll
    for (int h = 0; h < 8; h++)
        g_bias[((size_t)h * S + qrow) * S + kk] = vals[h];
}

// ---------------------------------------------------------------------------
// Kernel 3: QK + exp + mask rowsums ONLY (no attno writes), split-K=4.
// Same conflict-free micro as before.
// ---------------------------------------------------------------------------
__global__ void __launch_bounds__(128) qk_sum_kernel(const int* __restrict__ mask) {
    __shared__ float qsT[32][68];  // [d][q]
    __shared__ float ksT[32][68];  // [d][k]
    int bh = blockIdx.y;
    int b = bh >> 3;
    int q0 = blockIdx.x * 64;
    int sp = blockIdx.z;
    int t = threadIdx.x;
    int tx = t & 7, ty = t >> 3;   // tx: k columns, ty: 4q rows

    for (int i = t; i < 512; i += 128) {
        int r = i >> 4, c4 = (i & 15) * 4;
        *(float4*)&qsT[r][c4] = *(const float4*)&g_qhT[((size_t)bh * DK + r) * S + q0 + c4];
    }

    float rowacc[4] = {0.f, 0.f, 0.f, 0.f};
    const int* mbase = mask + (size_t)b * S * S;

    for (int kt = sp * 8; kt < sp * 8 + 8; kt++) {
        int kb = kt * 64;
        for (int i = t; i < 512; i += 128) {
            int r = i >> 4, c4 = (i & 15) * 4;
            *(float4*)&ksT[r][c4] = *(const float4*)&g_khT[((size_t)bh * DK + r) * S + kb + c4];
        }
        __syncthreads();

        ull acc2[4][4];
        #pragma unroll
        for (int i = 0; i < 4; i++)
            #pragma unroll
            for (int j = 0; j < 4; j++) acc2[i][j] = 0ull;

        #pragma unroll 8
        for (int d = 0; d < 32; d++) {
            float4 qv = *(const float4*)&qsT[d][ty * 4];
            ulonglong2 ka = *(const ulonglong2*)&ksT[d][tx * 4];
            ulonglong2 kb2 = *(const ulonglong2*)&ksT[d][tx * 4 + 32];
            ull qa2[4] = {pack2(qv.x, qv.x), pack2(qv.y, qv.y),
                          pack2(qv.z, qv.z), pack2(qv.w, qv.w)};
            #pragma unroll
            for (int qi = 0; qi < 4; qi++) {
                acc2[qi][0] = ffma2(qa2[qi], ka.x, acc2[qi][0]);
                acc2[qi][1] = ffma2(qa2[qi], ka.y, acc2[qi][1]);
                acc2[qi][2] = ffma2(qa2[qi], kb2.x, acc2[qi][2]);
                acc2[qi][3] = ffma2(qa2[qi], kb2.y, acc2[qi][3]);
            }
        }

        #pragma unroll
        for (int qi = 0; qi < 4; qi++) {
            int q = q0 + ty * 4 + qi;
            float2 a0 = unpack2(acc2[qi][0]);
            float2 a1 = unpack2(acc2[qi][1]);
            float2 a2v = unpack2(acc2[qi][2]);
            float2 a3 = unpack2(acc2[qi][3]);
            const int* mp = &mbase[(size_t)q * S + kb];
            int4 m0 = *(const int4*)&mp[tx * 4];
            int4 m1 = *(const int4*)&mp[tx * 4 + 32];
            float4 e0, e1;
            e0.x = m0.x ? fast_exp2(a0.x) : 0.f;
            e0.y = m0.y ? fast_exp2(a0.y) : 0.f;
            e0.z = m0.z ? fast_exp2(a1.x) : 0.f;
            e0.w = m0.w ? fast_exp2(a1.y) : 0.f;
            e1.x = m1.x ? fast_exp2(a2v.x) : 0.f;
            e1.y = m1.y ? fast_exp2(a2v.y) : 0.f;
            e1.z = m1.z ? fast_exp2(a3.x) : 0.f;
            e1.w = m1.w ? fast_exp2(a3.y) : 0.f;
            rowacc[qi] += ((e0.x + e0.y) + (e0.z + e0.w)) + ((e1.x + e1.y) + (e1.z + e1.w));
        }
        __syncthreads();
    }

    #pragma unroll
    for (int qi = 0; qi < 4; qi++) {
        float s = rowacc[qi];
        s += __shfl_xor_sync(0xffffffff, s, 4);
        s += __shfl_xor_sync(0xffffffff, s, 2);
        s += __shfl_xor_sync(0xffffffff, s, 1);
        if ((t & 7) == 0) g_rsum[sp * NBH * S + bh * S + q0 + ty * 4 + qi] = s;
    }
}

// ---------------------------------------------------------------------------
// Kernel 4: FUSED — recompute QK scores (bit-identical FFMA2 sequence),
// e = exp2, p = e*rinv -> write normalized attno (the only attno traffic),
// ps = p*bias built in smem straight from registers, then PV micro.
// Split-K=4 over k tiles; partials to g_part.
// ---------------------------------------------------------------------------
__global__ void __launch_bounds__(128) pv_fused_kernel(const int* __restrict__ mask,
                                                       float* __restrict__ attno) {
    __shared__ float qsT[32][68];   // [d][q]
    __shared__ float ksT[32][68];   // [d][k]
    __shared__ float vsT[32][68];   // [d][k]
    __shared__ float ps[64][68];    // [q][k] = p*bias
    __shared__ float rinv_s[64];
    int bh = blockIdx.y;
    int b = bh >> 3, h = bh & 7;
    int q0 = blockIdx.x * 64;
    int sp = blockIdx.z;
    int t = threadIdx.x;
    int tx = t & 7, ty = t >> 3;   // QK mapping: tx k-cols, ty 4q rows
    // PV mapping reuses tx (d = tx + 8*di) and ty as tq (q = ty + 16*qi)

    if (t < 64) {
        int i = bh * S + q0 + t;
        float s = g_rsum[i] + g_rsum[NBH * S + i]
                + g_rsum[2 * NBH * S + i] + g_rsum[3 * NBH * S + i];
        rinv_s[t] = 1.0f / s;
    }
    for (int i = t; i < 512; i += 128) {
        int r = i >> 4, c4 = (i & 15) * 4;
        *(float4*)&qsT[r][c4] = *(const float4*)&g_qhT[((size_t)bh * DK + r) * S + q0 + c4];
    }

    ull pacc[4][4];
    #pragma unroll
    for (int i = 0; i < 4; i++)
        #pragma unroll
        for (int j = 0; j < 4; j++) pacc[i][j] = 0ull;

    const float* biasb = g_bias + ((size_t)h * S + q0) * S;
    const int* mbase = mask + (size_t)b * S * S;

    for (int kt = sp * 8; kt < sp * 8 + 8; kt++) {
        int kb = kt * 64;
        for (int i = t; i < 512; i += 128) {
            int r = i >> 4, c4 = (i & 15) * 4;
            *(float4*)&ksT[r][c4] = *(const float4*)&g_khT[((size_t)bh * DK + r) * S + kb + c4];
            *(float4*)&vsT[r][c4] = *(const float4*)&g_vhT[((size_t)bh * DK + r) * S + kb + c4];
        }
        __syncthreads();

        // ---- QK micro (identical sequence to qk_sum) ----
        ull acc2[4][4];
        #pragma unroll
        for (int i = 0; i < 4; i++)
            #pragma unroll
            for (int j = 0; j < 4; j++) acc2[i][j] = 0ull;

        #pragma unroll 8
        for (int d = 0; d < 32; d++) {
            float4 qv = *(const float4*)&qsT[d][ty * 4];
            ulonglong2 ka = *(const ulonglong2*)&ksT[d][tx * 4];
            ulonglong2 kb2 = *(const ulonglong2*)&ksT[d][tx * 4 + 32];
            ull qa2[4] = {pack2(qv.x, qv.x), pack2(qv.y, qv.y),
                          pack2(qv.z, qv.z), pack2(qv.w, qv.w)};
            #pragma unroll
            for (int qi = 0; qi < 4; qi++) {
                acc2[qi][0] = ffma2(qa2[qi], ka.x, acc2[qi][0]);
                acc2[qi][1] = ffma2(qa2[qi], ka.y, acc2[qi][1]);
                acc2[qi][2] = ffma2(qa2[qi], kb2.x, acc2[qi][2]);
                acc2[qi][3] = ffma2(qa2[qi], kb2.y, acc2[qi][3]);
            }
        }

        // ---- epilogue: exp, mask, normalize, write attno, ps = p*bias ----
        #pragma unroll
        for (int qi = 0; qi < 4; qi++) {
            int qrow = ty * 4 + qi;
            int q = q0 + qrow;
            float r = rinv_s[qrow];
            float2 a0 = unpack2(acc2[qi][0]);
            float2 a1 = unpack2(acc2[qi][1]);
            float2 a2v = unpack2(acc2[qi][2]);
            float2 a3 = unpack2(acc2[qi][3]);
            const int* mp = &mbase[(size_t)q * S + kb];
            int4 m0 = *(const int4*)&mp[tx * 4];
            int4 m1 = *(const int4*)&mp[tx * 4 + 32];
            float4 p0, p1;
            p0.x = m0.x ? fast_exp2(a0.x) * r : 0.f;
            p0.y = m0.y ? fast_exp2(a0.y) * r : 0.f;
            p0.z = m0.z ? fast_exp2(a1.x) * r : 0.f;
            p0.w = m0.w ? fast_exp2(a1.y) * r : 0.f;
            p1.x = m1.x ? fast_exp2(a2v.x) * r : 0.f;
            p1.y = m1.y ? fast_exp2(a2v.y) * r : 0.f;
            p1.z = m1.z ? fast_exp2(a3.x) * r : 0.f;
            p1.w = m1.w ? fast_exp2(a3.y) * r : 0.f;
            float* ap = &attno[((size_t)bh * S + q) * S + kb];
            *(float4*)&ap[tx * 4] = p0;
            *(float4*)&ap[tx * 4 + 32] = p1;
            const float* bp = &biasb[(size_t)qrow * S + kb];
            float4 bb0 = *(const float4*)&bp[tx * 4];
            float4 bb1 = *(const float4*)&bp[tx * 4 + 32];
            *(float4*)&ps[qrow][tx * 4] =
                make_float4(p0.x * bb0.x, p0.y * bb0.y, p0.z * bb0.z, p0.w * bb0.w);
            *(float4*)&ps[qrow][tx * 4 + 32] =
                make_float4(p1.x * bb1.x, p1.y * bb1.y, p1.z * bb1.z, p1.w * bb1.w);
        }
        __syncthreads();

        // ---- PV micro (conflict-free, round-8 form) ----
        for (int kc = 0; kc < 64; kc += 4) {
            ulonglong2 v2[4];
            #pragma unroll
            for (int di = 0; di < 4; di++)
                v2[di] = *(const ulonglong2*)&vsT[tx + 8 * di][kc];
            #pragma unroll
            for (int qi = 0; qi < 4; qi++) {
                ulonglong2 p2 = *(const ulonglong2*)&ps[ty + 16 * qi][kc];
                #pragma unroll
                for (int di = 0; di < 4; di++) {
                    pacc[qi][di] = ffma2(p2.x, v2[di].x, pacc[qi][di]);
                    pacc[qi][di] = ffma2(p2.y, v2[di].y, pacc[qi][di]);
                }
            }
        }
        __syncthreads();
    }

    float* pout = g_part + (size_t)sp * NBH * S * DK;
    #pragma unroll
    for (int qi = 0; qi < 4; qi++) {
        int q = q0 + ty + 16 * qi;
        #pragma unroll
        for (int di = 0; di < 4; di++) {
            float2 v = unpack2(pacc[qi][di]);
            pout[((size_t)bh * S + q) * DK + tx + 8 * di] = v.x + v.y;
        }
    }
}

// ---------------------------------------------------------------------------
// Kernel 4b: reduce PVSPLIT partials into g_ctx [m][d] layout.
// ---------------------------------------------------------------------------
__global__ void pv_reduce_kernel() {
    int idx = blockIdx.x * 256 + threadIdx.x;
    int flat = idx * 4;
    float4 a = *(const float4*)&g_part[flat];
    #pragma unroll
    for (int sp = 1; sp < PVSPLIT; sp++) {
        float4 c = *(const float4*)&g_part[(size_t)sp * NBH * S * DK + flat];
        a.x += c.x; a.y += c.y; a.z += c.z; a.w += c.w;
    }
    int bh = flat >> 16;
    int rem = flat & 65535;
    int q = rem >> 5, dk = rem & 31;
    int b = bh >> 3, h = bh & 7;
    *(float4*)&g_ctx[((size_t)(q * B + b)) * D + h * DK + dk] = a;
}

// ---------------------------------------------------------------------------
// Kernel 5: fc GEMM + residual, FFMA2 inner loop.
// ---------------------------------------------------------------------------
__global__ void fc_kernel(const float* __restrict__ resid, const float* __restrict__ wfc) {
    __shared__ float asT[16][68];
    __shared__ float bs[16][68];
    int m0 = blockIdx.x * 64, n0 = blockIdx.y * 64;
    int t = threadIdx.x;
    int tx = t & 15, ty = t >> 4;
    int lrowA = t >> 2, lkA = (t & 3) * 4;
    int lkB = t >> 4, lnB = (t & 15) * 4;

    ull acc2[4][2];
    #pragma unroll
    for (int i = 0; i < 4; i++) { acc2[i][0] = 0ull; acc2[i][1] = 0ull; }

    for (int k0 = 0; k0 < D; k0 += 16) {
        float4 a4 = *(const float4*)&g_ctx[(size_t)(m0 + lrowA) * D + k0 + lkA];
        float4 b4 = *(const float4*)&wfc[(size_t)(k0 + lkB) * D + n0 + lnB];
        asT[lkA + 0][lrowA] = a4.x; asT[lkA + 1][lrowA] = a4.y;
        asT[lkA + 2][lrowA] = a4.z; asT[lkA + 3][lrowA] = a4.w;
        *(float4*)&bs[lkB][lnB] = b4;
        __syncthreads();
        #pragma unroll
        for (int kk = 0; kk < 16; kk++) {
            float4 av = *(const float4*)&asT[kk][ty * 4];
            const ull* bp = (const ull*)&bs[kk][tx * 4];
            ull b0 = bp[0], b1 = bp[1];
            ull a2[4] = {pack2(av.x, av.x), pack2(av.y, av.y),
                         pack2(av.z, av.z), pack2(av.w, av.w)};
            #pragma unroll
            for (int i = 0; i < 4; i++) {
                acc2[i][0] = ffma2(a2[i], b0, acc2[i][0]);
                acc2[i][1] = ffma2(a2[i], b1, acc2[i][1]);
            }
        }
        __syncthreads();
    }
    #pragma unroll
    for (int qi = 0; qi < 4; qi++) {
        int m = m0 + ty * 4 + qi;
        int n = n0 + tx * 4;
        float4 r4 = *(const float4*)&resid[(size_t)m * D + n];
        float2 lo = unpack2(acc2[qi][0]);
        float2 hi = unpack2(acc2[qi][1]);
        float4 o = make_float4(lo.x + r4.x, lo.y + r4.y, hi.x + r4.z, hi.y + r4.w);
        *(float4*)&g_fc[(size_t)m * D + n] = o;
    }
}

// ---------------------------------------------------------------------------
// Kernel 6: LayerNorm, warp per row.
// ---------------------------------------------------------------------------
__global__ void ln_kernel(const float* __restrict__ gamma, const float* __restrict__ beta,
                          float* __restrict__ out) {
    int m = blockIdx.x * 8 + (threadIdx.x >> 5);
    int lane = threadIdx.x & 31;
    const float* row = g_fc + (size_t)m * D;
    float4 v0 = *(const float4*)&row[lane * 4];
    float4 v1 = *(const float4*)&row[128 + lane * 4];
    float s1 = v0.x + v0.y + v0.z + v0.w + v1.x + v1.y + v1.z + v1.w;
    float s2 = v0.x * v0.x + v0.y * v0.y + v0.z * v0.z + v0.w * v0.w
             + v1.x * v1.x + v1.y * v1.y + v1.z * v1.z + v1.w * v1.w;
    #pragma unroll
    for (int o = 16; o > 0; o >>= 1) {
        s1 += __shfl_xor_sync(0xffffffff, s1, o);
        s2 += __shfl_xor_sync(0xffffffff, s2, o);
    }
    float mu = s1 * (1.0f / 256.0f);
    float var = s2 * (1.0f / 256.0f) - mu * mu;
    float rstd = rsqrtf(var + 1e-6f);
    float4 g0 = *(const float4*)&gamma[lane * 4];
    float4 g1 = *(const float4*)&gamma[128 + lane * 4];
    float4 b0 = *(const float4*)&beta[lane * 4];
    float4 b1 = *(const float4*)&beta[128 + lane * 4];
    float4 o0 = make_float4((v0.x - mu) * rstd * g0.x + b0.x,
                            (v0.y - mu) * rstd * g0.y + b0.y,
                            (v0.z - mu) * rstd * g0.z + b0.z,
                            (v0.w - mu) * rstd * g0.w + b0.w);
    float4 o1 = make_float4((v1.x - mu) * rstd * g1.x + b1.x,
                            (v1.y - mu) * rstd * g1.y + b1.y,
                            (v1.z - mu) * rstd * g1.z + b1.z,
                            (v1.w - mu) * rstd * g1.w + b1.w);
    *(float4*)&out[(size_t)m * D + lane * 4] = o0;
    *(float4*)&out[(size_t)m * D + 128 + lane * 4] = o1;
}

extern "C" void kernel_launch(void* const* d_in, const int* in_sizes, int n_in,
                              void* d_out, int out_size) {
    const float* q     = (const float*)d_in[0];
    const float* k     = (const float*)d_in[1];
    const float* v     = (const float*)d_in[2];
    const float* gp    = (const float*)d_in[3];
    const int*   mask  = (const int*)d_in[4];
    const float* wq    = (const float*)d_in[5];
    const float* wk    = (const float*)d_in[6];
    const float* wv    = (const float*)d_in[7];
    const float* wfc   = (const float*)d_in[8];
    const float* gamma = (const float*)d_in[9];
    const float* beta  = (const float*)d_in[10];

    float* out = (float*)d_out;
    float* attno = out + (size_t)S * B * D;

    bias_transpose_kernel<<<dim3(S / 256, S), 256>>>(gp);
    proj_kernel<<<dim3(S * B / 64, D / 64, 3), 256>>>(q, k, v, wq, wk, wv);
    head_transpose_kernel<<<dim3(S / 64, NBH, 3), 128>>>();
    qk_sum_kernel<<<dim3(S / 64, NBH, SPLIT), 128>>>(mask);
    pv_fused_kernel<<<dim3(S / 64, NBH, PVSPLIT), 128>>>(mask, attno);
    pv_reduce_kernel<<<NBH * S * DK / 4 / 256, 256>>>();
    fc_kernel<<<dim3(S * B / 64, D / 64), 256>>>(q, wfc);
    ln_kernel<<<S * B / 8, 256>>>(gamma, beta, out);
}

// round 11
// speedup vs baseline: 1.1208x; 1.1208x over previous
#include <cuda_runtime.h>
#include <math.h>

#define S 2048
#define B 2
#define D 256
#define H 8
#define DK 32
#define NBH 16
#define SPLIT 4
#define PVSPLIT 4
// fold log2(e)/sqrt(DK) into Q at projection time; then exp(s) == exp2(acc)
#define QSCALE (1.4426950408889634f * 0.17677669529663687f)

typedef unsigned long long ull;

__device__ float g_qh[NBH * S * DK];        // [bh, s, dk]
__device__ float g_kh[NBH * S * DK];
__device__ float g_vh[NBH * S * DK];
__device__ float g_qhT[NBH * DK * S];       // [bh, dk, s]
__device__ float g_khT[NBH * DK * S];
__device__ float g_vhT[NBH * DK * S];
__device__ float g_bias[(size_t)H * S * S]; // [h, q, k]
__device__ float g_rsum[SPLIT * NBH * S];   // partial rowsums from qk
__device__ float g_part[PVSPLIT * NBH * S * DK]; // pv split-k partials
__device__ float g_ctx[S * B * D];          // [m = s*B+b, d]
__device__ float g_fc[S * B * D];           // fc output + residual

__device__ __forceinline__ float fast_exp2(float x) {
    float r;
    asm("ex2.approx.f32 %0, %1;" : "=f"(r) : "f"(x));
    return r;
}
// packed fp32x2 FMA (Blackwell): d = a*b + c lanewise, rn rounding (== fmaf)
__device__ __forceinline__ ull ffma2(ull a, ull b, ull c) {
    ull d;
    asm("fma.rn.f32x2 %0, %1, %2, %3;" : "=l"(d) : "l"(a), "l"(b), "l"(c));
    return d;
}
__device__ __forceinline__ ull pack2(float x, float y) {
    ull r;
    asm("mov.b64 %0, {%1, %2};" : "=l"(r) : "f"(x), "f"(y));
    return r;
}
__device__ __forceinline__ float2 unpack2(ull v) {
    float2 r;
    asm("mov.b64 {%0, %1}, %2;" : "=f"(r.x), "=f"(r.y) : "l"(v));
    return r;
}

// ---------------------------------------------------------------------------
// Kernel 1: QKV projections. 64x64 tile SGEMM, 256 threads, 4x4 micro-tile.
// ---------------------------------------------------------------------------
__global__ void proj_kernel(const float* __restrict__ q, const float* __restrict__ k,
                            const float* __restrict__ v,
                            const float* __restrict__ wq, const float* __restrict__ wk,
                            const float* __restrict__ wv) {
    __shared__ float asT[16][68];  // [k][m]
    __shared__ float bs[16][68];   // [k][n]
    int which = blockIdx.z;
    const float* x = (which == 0) ? q : (which == 1 ? k : v);
    const float* w = (which == 0) ? wq : (which == 1 ? wk : wv);
    float* out = (which == 0) ? g_qh : (which == 1 ? g_kh : g_vh);

    int m0 = blockIdx.x * 64, n0 = blockIdx.y * 64;
    int t = threadIdx.x;
    int tx = t & 15, ty = t >> 4;
    int lrowA = t >> 2, lkA = (t & 3) * 4;
    int lkB = t >> 4, lnB = (t & 15) * 4;

    ull acc2[4][2];
    #pragma unroll
    for (int i = 0; i < 4; i++) { acc2[i][0] = 0ull; acc2[i][1] = 0ull; }

    for (int k0 = 0; k0 < D; k0 += 16) {
        float4 a4 = *(const float4*)&x[(size_t)(m0 + lrowA) * D + k0 + lkA];
        float4 b4 = *(const float4*)&w[(size_t)(k0 + lkB) * D + n0 + lnB];
        asT[lkA + 0][lrowA] = a4.x; asT[lkA + 1][lrowA] = a4.y;
        asT[lkA + 2][lrowA] = a4.z; asT[lkA + 3][lrowA] = a4.w;
        *(float4*)&bs[lkB][lnB] = b4;
        __syncthreads();
        #pragma unroll
        for (int kk = 0; kk < 16; kk++) {
            float4 av = *(const float4*)&asT[kk][ty * 4];
            const ull* bp = (const ull*)&bs[kk][tx * 4];
            ull b0 = bp[0], b1 = bp[1];
            ull a2[4] = {pack2(av.x, av.x), pack2(av.y, av.y),
                         pack2(av.z, av.z), pack2(av.w, av.w)};
            #pragma unroll
            for (int i = 0; i < 4; i++) {
                acc2[i][0] = ffma2(a2[i], b0, acc2[i][0]);
                acc2[i][1] = ffma2(a2[i], b1, acc2[i][1]);
            }
        }
        __syncthreads();
    }
    float sc = (which == 0) ? QSCALE : 1.0f;
    int n = n0 + tx * 4;
    int h = n >> 5, dk = n & 31;
    #pragma unroll
    for (int qi = 0; qi < 4; qi++) {
        int m = m0 + ty * 4 + qi;
        int b = m & 1, s = m >> 1;
        float2 lo = unpack2(acc2[qi][0]);
        float2 hi = unpack2(acc2[qi][1]);
        float4 o = make_float4(lo.x * sc, lo.y * sc, hi.x * sc, hi.y * sc);
        *(float4*)&out[((size_t)(b * H + h) * S + s) * DK + dk] = o;
    }
}

// ---------------------------------------------------------------------------
// Kernel 1b: transpose heads [bh, s, dk] -> [bh, dk, s] for Q, K, V.
// ---------------------------------------------------------------------------
__global__ void head_transpose_kernel() {
    __shared__ float ts[64][33];
    int z = blockIdx.z;
    const float* src = (z == 0) ? g_qh : (z == 1 ? g_kh : g_vh);
    float* dst = (z == 0) ? g_qhT : (z == 1 ? g_khT : g_vhT);
    int bh = blockIdx.y;
    int s0 = blockIdx.x * 64;
    int t = threadIdx.x;

    for (int i = t; i < 512; i += 128) {
        int r = i >> 3, d4 = (i & 7) * 4;
        float4 a = *(const float4*)&src[((size_t)bh * S + s0 + r) * DK + d4];
        ts[r][d4 + 0] = a.x; ts[r][d4 + 1] = a.y;
        ts[r][d4 + 2] = a.z; ts[r][d4 + 3] = a.w;
    }
    __syncthreads();

    int d = t >> 2, c = t & 3;
    #pragma unroll
    for (int iter = 0; iter < 4; iter++) {
        int sl = c * 4 + iter * 16;
        float4 o = make_float4(ts[sl + 0][d], ts[sl + 1][d], ts[sl + 2][d], ts[sl + 3][d]);
        *(float4*)&dst[((size_t)bh * DK + d) * S + s0 + sl] = o;
    }
}

// ---------------------------------------------------------------------------
// Kernel 2: transpose graph_pos [k,q,h] -> g_bias [h,q,k]. Streaming stores.
// ---------------------------------------------------------------------------
__global__ void bias_transpose_kernel(const float* __restrict__ gp) {
    int qrow = blockIdx.y;
    int kk = blockIdx.x * 256 + threadIdx.x;
    const float4* p = reinterpret_cast<const float4*>(gp + ((size_t)kk * S + qrow) * H);
    float4 a = __ldcs(p);
    float4 b4 = __ldcs(p + 1);
    float vals[8] = {a.x, a.y, a.z, a.w, b4.x, b4.y, b4.z, b4.w};
    #pragma unroll
    for (int h = 0; h < 8; h++)
        __stcs(&g_bias[((size_t)h * S + qrow) * S + kk], vals[h]);
}

// ---------------------------------------------------------------------------
// Kernel 3: QK + exp + mask, split-K=4. Conflict-free LDS.128, FFMA2 pairs.
// Unnormalized exp streamed out with .cs (touch-once); rowsums to g_rsum.
// ---------------------------------------------------------------------------
__global__ void __launch_bounds__(128) qk_kernel(const int* __restrict__ mask,
                                                 float* __restrict__ attno) {
    __shared__ float qsT[32][68];  // [d][q]
    __shared__ float ksT[32][68];  // [d][k]
    int bh = blockIdx.y;
    int b = bh >> 3;
    int q0 = blockIdx.x * 64;
    int sp = blockIdx.z;
    int t = threadIdx.x;
    int tx = t & 7, ty = t >> 3;   // tx: k columns, ty: 4q rows

    for (int i = t; i < 512; i += 128) {
        int r = i >> 4, c4 = (i & 15) * 4;
        *(float4*)&qsT[r][c4] = *(const float4*)&g_qhT[((size_t)bh * DK + r) * S + q0 + c4];
    }

    float rowacc[4] = {0.f, 0.f, 0.f, 0.f};
    const int* mbase = mask + (size_t)b * S * S;

    for (int kt = sp * 8; kt < sp * 8 + 8; kt++) {
        int kb = kt * 64;
        for (int i = t; i < 512; i += 128) {
            int r = i >> 4, c4 = (i & 15) * 4;
            *(float4*)&ksT[r][c4] = *(const float4*)&g_khT[((size_t)bh * DK + r) * S + kb + c4];
        }
        __syncthreads();

        ull acc2[4][4];
        #pragma unroll
        for (int i = 0; i < 4; i++)
            #pragma unroll
            for (int j = 0; j < 4; j++) acc2[i][j] = 0ull;

        #pragma unroll 8
        for (int d = 0; d < 32; d++) {
            float4 qv = *(const float4*)&qsT[d][ty * 4];
            ulonglong2 ka = *(const ulonglong2*)&ksT[d][tx * 4];
            ulonglong2 kb2 = *(const ulonglong2*)&ksT[d][tx * 4 + 32];
            ull qa2[4] = {pack2(qv.x, qv.x), pack2(qv.y, qv.y),
                          pack2(qv.z, qv.z), pack2(qv.w, qv.w)};
            #pragma unroll
            for (int qi = 0; qi < 4; qi++) {
                acc2[qi][0] = ffma2(qa2[qi], ka.x, acc2[qi][0]);
                acc2[qi][1] = ffma2(qa2[qi], ka.y, acc2[qi][1]);
                acc2[qi][2] = ffma2(qa2[qi], kb2.x, acc2[qi][2]);
                acc2[qi][3] = ffma2(qa2[qi], kb2.y, acc2[qi][3]);
            }
        }

        #pragma unroll
        for (int qi = 0; qi < 4; qi++) {
            int q = q0 + ty * 4 + qi;
            float2 a0 = unpack2(acc2[qi][0]);
            float2 a1 = unpack2(acc2[qi][1]);
            float2 a2v = unpack2(acc2[qi][2]);
            float2 a3 = unpack2(acc2[qi][3]);
            const int* mp = &mbase[(size_t)q * S + kb];
            int4 m0 = __ldcs((const int4*)&mp[tx * 4]);
            int4 m1 = __ldcs((const int4*)&mp[tx * 4 + 32]);
            float4 e0, e1;
            e0.x = m0.x ? fast_exp2(a0.x) : 0.f;
            e0.y = m0.y ? fast_exp2(a0.y) : 0.f;
            e0.z = m0.z ? fast_exp2(a1.x) : 0.f;
            e0.w = m0.w ? fast_exp2(a1.y) : 0.f;
            e1.x = m1.x ? fast_exp2(a2v.x) : 0.f;
            e1.y = m1.y ? fast_exp2(a2v.y) : 0.f;
            e1.z = m1.z ? fast_exp2(a3.x) : 0.f;
            e1.w = m1.w ? fast_exp2(a3.y) : 0.f;
            float* ap = &attno[((size_t)bh * S + q) * S + kb];
            __stcs((float4*)&ap[tx * 4], e0);
            __stcs((float4*)&ap[tx * 4 + 32], e1);
            rowacc[qi] += ((e0.x + e0.y) + (e0.z + e0.w)) + ((e1.x + e1.y) + (e1.z + e1.w));
        }
        __syncthreads();
    }

    #pragma unroll
    for (int qi = 0; qi < 4; qi++) {
        float s = rowacc[qi];
        s += __shfl_xor_sync(0xffffffff, s, 4);
        s += __shfl_xor_sync(0xffffffff, s, 2);
        s += __shfl_xor_sync(0xffffffff, s, 1);
        if ((t & 7) == 0) g_rsum[sp * NBH * S + bh * S + q0 + ty * 4 + qi] = s;
    }
}

// ---------------------------------------------------------------------------
// Kernel 4: normalize attno in place, PV GEMM on (p*bias), split-K=4.
// Touch-once streams (attno, bias, partials) use .cs; V tiles stay cached.
// ---------------------------------------------------------------------------
__global__ void __launch_bounds__(128, 8) pv_kernel(float* __restrict__ attno) {
    __shared__ float ps[64][68];    // [q][k]
    __shared__ float vsT[32][68];   // [d][k]
    __shared__ float rinv_s[64];
    int bh = blockIdx.y;
    int h = bh & 7;
    int q0 = blockIdx.x * 64;
    int sp = blockIdx.z;
    int t = threadIdx.x;
    int tx = t & 7;       // d = tx + 8*di
    int tq = t >> 3;      // 0..15, q = tq + 16*qi

    if (t < 64) {
        int i = bh * S + q0 + t;
        float s = g_rsum[i] + g_rsum[NBH * S + i]
                + g_rsum[2 * NBH * S + i] + g_rsum[3 * NBH * S + i];
        rinv_s[t] = 1.0f / s;
    }
    __syncthreads();

    ull acc2[4][4];
    #pragma unroll
    for (int i = 0; i < 4; i++)
        #pragma unroll
        for (int j = 0; j < 4; j++) acc2[i][j] = 0ull;

    const float* biasb = g_bias + ((size_t)h * S + q0) * S;
    float* ab = attno + ((size_t)bh * S + q0) * S;

    for (int kt = sp * 8; kt < sp * 8 + 8; kt++) {
        int kb = kt * 64;
        // V tile [d][k] straight from transposed layout (reused across blocks)
        for (int i = t; i < 512; i += 128) {
            int r = i >> 4, c4 = (i & 15) * 4;
            *(float4*)&vsT[r][c4] = *(const float4*)&g_vhT[((size_t)bh * DK + r) * S + kb + c4];
        }
        // attno normalize + writeback + ps = p*bias (all touch-once: .cs)
        for (int i = t; i < 1024; i += 128) {
            int row = i >> 4, c4 = (i & 15) * 4;
            float4 e = __ldcs((const float4*)&ab[(size_t)row * S + kb + c4]);
            float4 bb = __ldcs((const float4*)&biasb[(size_t)row * S + kb + c4]);
            float r = rinv_s[row];
            e.x *= r; e.y *= r; e.z *= r; e.w *= r;
            __stcs((float4*)&ab[(size_t)row * S + kb + c4], e);  // final normalized attno
            *(float4*)&ps[row][c4] = make_float4(e.x * bb.x, e.y * bb.y,
                                                 e.z * bb.z, e.w * bb.w);
        }
        __syncthreads();

        for (int kc = 0; kc < 64; kc += 4) {
            ulonglong2 v2[4];
            #pragma unroll
            for (int di = 0; di < 4; di++)
                v2[di] = *(const ulonglong2*)&vsT[tx + 8 * di][kc];
            #pragma unroll
            for (int qi = 0; qi < 4; qi++) {
                ulonglong2 p2 = *(const ulonglong2*)&ps[tq + 16 * qi][kc];
                #pragma unroll
                for (int di = 0; di < 4; di++) {
                    acc2[qi][di] = ffma2(p2.x, v2[di].x, acc2[qi][di]);
                    acc2[qi][di] = ffma2(p2.y, v2[di].y, acc2[qi][di]);
                }
            }
        }
        __syncthreads();
    }

    float* pout = g_part + (size_t)sp * NBH * S * DK;
    #pragma unroll
    for (int qi = 0; qi < 4; qi++) {
        int q = q0 + tq + 16 * qi;
        #pragma unroll
        for (int di = 0; di < 4; di++) {
            float2 v = unpack2(acc2[qi][di]);
            __stcs(&pout[((size_t)bh * S + q) * DK + tx + 8 * di], v.x + v.y);
        }
    }
}

// ---------------------------------------------------------------------------
// Kernel 4b: reduce PVSPLIT partials into g_ctx [m][d] layout.
// ---------------------------------------------------------------------------
__global__ void pv_reduce_kernel() {
    int idx = blockIdx.x * 256 + threadIdx.x;
    int flat = idx * 4;
    float4 a = __ldcs((const float4*)&g_part[flat]);
    #pragma unroll
    for (int sp = 1; sp < PVSPLIT; sp++) {
        float4 c = __ldcs((const float4*)&g_part[(size_t)sp * NBH * S * DK + flat]);
        a.x += c.x; a.y += c.y; a.z += c.z; a.w += c.w;
    }
    int bh = flat >> 16;
    int rem = flat & 65535;
    int q = rem >> 5, dk = rem & 31;
    int b = bh >> 3, h = bh & 7;
    *(float4*)&g_ctx[((size_t)(q * B + b)) * D + h * DK + dk] = a;
}

// ---------------------------------------------------------------------------
// Kernel 5: fc GEMM + residual, FFMA2 inner loop.
// ---------------------------------------------------------------------------
__global__ void fc_kernel(const float* __restrict__ resid, const float* __restrict__ wfc) {
    __shared__ float asT[16][68];
    __shared__ float bs[16][68];
    int m0 = blockIdx.x * 64, n0 = blockIdx.y * 64;
    int t = threadIdx.x;
    int tx = t & 15, ty = t >> 4;
    int lrowA = t >> 2, lkA = (t & 3) * 4;
    int lkB = t >> 4, lnB = (t & 15) * 4;

    ull acc2[4][2];
    #pragma unroll
    for (int i = 0; i < 4; i++) { acc2[i][0] = 0ull; acc2[i][1] = 0ull; }

    for (int k0 = 0; k0 < D; k0 += 16) {
        float4 a4 = *(const float4*)&g_ctx[(size_t)(m0 + lrowA) * D + k0 + lkA];
        float4 b4 = *(const float4*)&wfc[(size_t)(k0 + lkB) * D + n0 + lnB];
        asT[lkA + 0][lrowA] = a4.x; asT[lkA + 1][lrowA] = a4.y;
        asT[lkA + 2][lrowA] = a4.z; asT[lkA + 3][lrowA] = a4.w;
        *(float4*)&bs[lkB][lnB] = b4;
        __syncthreads();
        #pragma unroll
        for (int kk = 0; kk < 16; kk++) {
            float4 av = *(const float4*)&asT[kk][ty * 4];
            const ull* bp = (const ull*)&bs[kk][tx * 4];
            ull b0 = bp[0], b1 = bp[1];
            ull a2[4] = {pack2(av.x, av.x), pack2(av.y, av.y),
                         pack2(av.z, av.z), pack2(av.w, av.w)};
            #pragma unroll
            for (int i = 0; i < 4; i++) {
                acc2[i][0] = ffma2(a2[i], b0, acc2[i][0]);
                acc2[i][1] = ffma2(a2[i], b1, acc2[i][1]);
            }
        }
        __syncthreads();
    }
    #pragma unroll
    for (int qi = 0; qi < 4; qi++) {
        int m = m0 + ty * 4 + qi;
        int n = n0 + tx * 4;
        float4 r4 = *(const float4*)&resid[(size_t)m * D + n];
        float2 lo = unpack2(acc2[qi][0]);
        float2 hi = unpack2(acc2[qi][1]);
        float4 o = make_float4(lo.x + r4.x, lo.y + r4.y, hi.x + r4.z, hi.y + r4.w);
        *(float4*)&g_fc[(size_t)m * D + n] = o;
    }
}

// ---------------------------------------------------------------------------
// Kernel 6: LayerNorm, warp per row.
// ---------------------------------------------------------------------------
__global__ void ln_kernel(const float* __restrict__ gamma, const float* __restrict__ beta,
                          float* __restrict__ out) {
    int m = blockIdx.x * 8 + (threadIdx.x >> 5);
    int lane = threadIdx.x & 31;
    const float* row = g_fc + (size_t)m * D;
    float4 v0 = *(const float4*)&row[lane * 4];
    float4 v1 = *(const float4*)&row[128 + lane * 4];
    float s1 = v0.x + v0.y + v0.z + v0.w + v1.x + v1.y + v1.z + v1.w;
    float s2 = v0.x * v0.x + v0.y * v0.y + v0.z * v0.z + v0.w * v0.w
             + v1.x * v1.x + v1.y * v1.y + v1.z * v1.z + v1.w * v1.w;
    #pragma unroll
    for (int o = 16; o > 0; o >>= 1) {
        s1 += __shfl_xor_sync(0xffffffff, s1, o);
        s2 += __shfl_xor_sync(0xffffffff, s2, o);
    }
    float mu = s1 * (1.0f / 256.0f);
    float var = s2 * (1.0f / 256.0f) - mu * mu;
    float rstd = rsqrtf(var + 1e-6f);
    float4 g0 = *(const float4*)&gamma[lane * 4];
    float4 g1 = *(const float4*)&gamma[128 + lane * 4];
    float4 b0 = *(const float4*)&beta[lane * 4];
    float4 b1 = *(const float4*)&beta[128 + lane * 4];
    float4 o0 = make_float4((v0.x - mu) * rstd * g0.x + b0.x,
                            (v0.y - mu) * rstd * g0.y + b0.y,
                            (v0.z - mu) * rstd * g0.z + b0.z,
                            (v0.w - mu) * rstd * g0.w + b0.w);
    float4 o1 = make_float4((v1.x - mu) * rstd * g1.x + b1.x,
                            (v1.y - mu) * rstd * g1.y + b1.y,
                            (v1.z - mu) * rstd * g1.z + b1.z,
                            (v1.w - mu) * rstd * g1.w + b1.w);
    *(float4*)&out[(size_t)m * D + lane * 4] = o0;
    *(float4*)&out[(size_t)m * D + 128 + lane * 4] = o1;
}

extern "C" void kernel_launch(void* const* d_in, const int* in_sizes, int n_in,
                              void* d_out, int out_size) {
    const float* q     = (const float*)d_in[0];
    const float* k     = (const float*)d_in[1];
    const float* v     = (const float*)d_in[2];
    const float* gp    = (const float*)d_in[3];
    const int*   mask  = (const int*)d_in[4];
    const float* wq    = (const float*)d_in[5];
    const float* wk    = (const float*)d_in[6];
    const float* wv    = (const float*)d_in[7];
    const float* wfc   = (const float*)d_in[8];
    const float* gamma = (const float*)d_in[9];
    const float* beta  = (const float*)d_in[10];

    float* out = (float*)d_out;
    float* attno = out + (size_t)S * B * D;

    bias_transpose_kernel<<<dim3(S / 256, S), 256>>>(gp);
    proj_kernel<<<dim3(S * B / 64, D / 64, 3), 256>>>(q, k, v, wq, wk, wv);
    head_transpose_kernel<<<dim3(S / 64, NBH, 3), 128>>>();
    qk_kernel<<<dim3(S / 64, NBH, SPLIT), 128>>>(mask, attno);
    pv_kernel<<<dim3(S / 64, NBH, PVSPLIT), 128>>>(attno);
    pv_reduce_kernel<<<NBH * S * DK / 4 / 256, 256>>>();
    fc_kernel<<<dim3(S * B / 64, D / 64), 256>>>(q, wfc);
    ln_kernel<<<S * B / 8, 256>>>(gamma, beta, out);
}

// round 12
// speedup vs baseline: 1.1214x; 1.0005x over previous
#include <cuda_runtime.h>
#include <math.h>

#define S 2048
#define B 2
#define D 256
#define H 8
#define DK 32
#define NBH 16
#define SPLIT 4
#define PVSPLIT 4
// fold log2(e)/sqrt(DK) into Q at projection time; then exp(s) == exp2(acc)
#define QSCALE (1.4426950408889634f * 0.17677669529663687f)

typedef unsigned long long ull;

__device__ float g_qh[NBH * S * DK];        // [bh, s, dk]
__device__ float g_kh[NBH * S * DK];
__device__ float g_vh[NBH * S * DK];
__device__ float g_qhT[NBH * DK * S];       // [bh, dk, s]
__device__ float g_khT[NBH * DK * S];
__device__ float g_vhT[NBH * DK * S];
__device__ float g_bias[(size_t)H * S * S]; // [h, q, k]
__device__ float g_rsum[SPLIT * NBH * S];   // partial rowsums from qk
__device__ float g_part[PVSPLIT * NBH * S * DK]; // pv split-k partials
__device__ float g_ctx[S * B * D];          // [m = s*B+b, d]
__device__ float g_fc[S * B * D];           // fc output + residual

__device__ __forceinline__ float fast_exp2(float x) {
    float r;
    asm("ex2.approx.f32 %0, %1;" : "=f"(r) : "f"(x));
    return r;
}
// packed fp32x2 FMA (Blackwell): d = a*b + c lanewise, rn rounding (== fmaf)
__device__ __forceinline__ ull ffma2(ull a, ull b, ull c) {
    ull d;
    asm("fma.rn.f32x2 %0, %1, %2, %3;" : "=l"(d) : "l"(a), "l"(b), "l"(c));
    return d;
}
__device__ __forceinline__ ull pack2(float x, float y) {
    ull r;
    asm("mov.b64 %0, {%1, %2};" : "=l"(r) : "f"(x), "f"(y));
    return r;
}
__device__ __forceinline__ float2 unpack2(ull v) {
    float2 r;
    asm("mov.b64 {%0, %1}, %2;" : "=f"(r.x), "=f"(r.y) : "l"(v));
    return r;
}

// ---------------------------------------------------------------------------
// Kernel 1: QKV projections. 64x64 tile SGEMM, 256 threads, 4x4 micro-tile.
// ---------------------------------------------------------------------------
__global__ void proj_kernel(const float* __restrict__ q, const float* __restrict__ k,
                            const float* __restrict__ v,
                            const float* __restrict__ wq, const float* __restrict__ wk,
                            const float* __restrict__ wv) {
    __shared__ float asT[16][68];  // [k][m]
    __shared__ float bs[16][68];   // [k][n]
    int which = blockIdx.z;
    const float* x = (which == 0) ? q : (which == 1 ? k : v);
    const float* w = (which == 0) ? wq : (which == 1 ? wk : wv);
    float* out = (which == 0) ? g_qh : (which == 1 ? g_kh : g_vh);

    int m0 = blockIdx.x * 64, n0 = blockIdx.y * 64;
    int t = threadIdx.x;
    int tx = t & 15, ty = t >> 4;
    int lrowA = t >> 2, lkA = (t & 3) * 4;
    int lkB = t >> 4, lnB = (t & 15) * 4;

    ull acc2[4][2];
    #pragma unroll
    for (int i = 0; i < 4; i++) { acc2[i][0] = 0ull; acc2[i][1] = 0ull; }

    for (int k0 = 0; k0 < D; k0 += 16) {
        float4 a4 = *(const float4*)&x[(size_t)(m0 + lrowA) * D + k0 + lkA];
        float4 b4 = *(const float4*)&w[(size_t)(k0 + lkB) * D + n0 + lnB];
        asT[lkA + 0][lrowA] = a4.x; asT[lkA + 1][lrowA] = a4.y;
        asT[lkA + 2][lrowA] = a4.z; asT[lkA + 3][lrowA] = a4.w;
        *(float4*)&bs[lkB][lnB] = b4;
        __syncthreads();
        #pragma unroll
        for (int kk = 0; kk < 16; kk++) {
            float4 av = *(const float4*)&asT[kk][ty * 4];
            const ull* bp = (const ull*)&bs[kk][tx * 4];
            ull b0 = bp[0], b1 = bp[1];
            ull a2[4] = {pack2(av.x, av.x), pack2(av.y, av.y),
                         pack2(av.z, av.z), pack2(av.w, av.w)};
            #pragma unroll
            for (int i = 0; i < 4; i++) {
                acc2[i][0] = ffma2(a2[i], b0, acc2[i][0]);
                acc2[i][1] = ffma2(a2[i], b1, acc2[i][1]);
            }
        }
        __syncthreads();
    }
    float sc = (which == 0) ? QSCALE : 1.0f;
    int n = n0 + tx * 4;
    int h = n >> 5, dk = n & 31;
    #pragma unroll
    for (int qi = 0; qi < 4; qi++) {
        int m = m0 + ty * 4 + qi;
        int b = m & 1, s = m >> 1;
        float2 lo = unpack2(acc2[qi][0]);
        float2 hi = unpack2(acc2[qi][1]);
        float4 o = make_float4(lo.x * sc, lo.y * sc, hi.x * sc, hi.y * sc);
        *(float4*)&out[((size_t)(b * H + h) * S + s) * DK + dk] = o;
    }
}

// ---------------------------------------------------------------------------
// Kernel 1b: transpose heads [bh, s, dk] -> [bh, dk, s] for Q, K, V.
// ---------------------------------------------------------------------------
__global__ void head_transpose_kernel() {
    __shared__ float ts[64][33];
    int z = blockIdx.z;
    const float* src = (z == 0) ? g_qh : (z == 1 ? g_kh : g_vh);
    float* dst = (z == 0) ? g_qhT : (z == 1 ? g_khT : g_vhT);
    int bh = blockIdx.y;
    int s0 = blockIdx.x * 64;
    int t = threadIdx.x;

    for (int i = t; i < 512; i += 128) {
        int r = i >> 3, d4 = (i & 7) * 4;
        float4 a = *(const float4*)&src[((size_t)bh * S + s0 + r) * DK + d4];
        ts[r][d4 + 0] = a.x; ts[r][d4 + 1] = a.y;
        ts[r][d4 + 2] = a.z; ts[r][d4 + 3] = a.w;
    }
    __syncthreads();

    int d = t >> 2, c = t & 3;
    #pragma unroll
    for (int iter = 0; iter < 4; iter++) {
        int sl = c * 4 + iter * 16;
        float4 o = make_float4(ts[sl + 0][d], ts[sl + 1][d], ts[sl + 2][d], ts[sl + 3][d]);
        *(float4*)&dst[((size_t)bh * DK + d) * S + s0 + sl] = o;
    }
}

// ---------------------------------------------------------------------------
// Kernel 3 (MERGED): z in [0,SPLIT) -> QK + exp + mask (split-K).
//                    z >= SPLIT     -> bias transpose blocks (memory-bound,
//                    overlapped behind the compute blocks in the same launch).
// ---------------------------------------------------------------------------
__global__ void __launch_bounds__(128) qk_bias_kernel(const int* __restrict__ mask,
                                                      float* __restrict__ attno,
                                                      const float* __restrict__ gp) {
    __shared__ float qsT[32][68];  // [d][q]
    __shared__ float ksT[32][68];  // [d][k]

    if (blockIdx.z >= SPLIT) {
        // ---- bias transpose: graph_pos [k,q,h] -> g_bias [h,q,k] ----
        int flat = blockIdx.x + 32 * blockIdx.y + 512 * (blockIdx.z - SPLIT); // [0,32768)
        int qrow = flat >> 4;
        int kk = (flat & 15) * 128 + threadIdx.x;
        const float4* p = reinterpret_cast<const float4*>(gp + ((size_t)kk * S + qrow) * H);
        float4 a = p[0];
        float4 b4 = p[1];
        float vals[8] = {a.x, a.y, a.z, a.w, b4.x, b4.y, b4.z, b4.w};
        #pragma unroll
        for (int h = 0; h < 8; h++)
            g_bias[((size_t)h * S + qrow) * S + kk] = vals[h];
        return;
    }

    int bh = blockIdx.y;
    int b = bh >> 3;
    int q0 = blockIdx.x * 64;
    int sp = blockIdx.z;
    int t = threadIdx.x;
    int tx = t & 7, ty = t >> 3;   // tx: k columns, ty: 4q rows

    for (int i = t; i < 512; i += 128) {
        int r = i >> 4, c4 = (i & 15) * 4;
        *(float4*)&qsT[r][c4] = *(const float4*)&g_qhT[((size_t)bh * DK + r) * S + q0 + c4];
    }

    float rowacc[4] = {0.f, 0.f, 0.f, 0.f};
    const int* mbase = mask + (size_t)b * S * S;

    for (int kt = sp * 8; kt < sp * 8 + 8; kt++) {
        int kb = kt * 64;
        for (int i = t; i < 512; i += 128) {
            int r = i >> 4, c4 = (i & 15) * 4;
            *(float4*)&ksT[r][c4] = *(const float4*)&g_khT[((size_t)bh * DK + r) * S + kb + c4];
        }
        __syncthreads();

        ull acc2[4][4];
        #pragma unroll
        for (int i = 0; i < 4; i++)
            #pragma unroll
            for (int j = 0; j < 4; j++) acc2[i][j] = 0ull;

        #pragma unroll 8
        for (int d = 0; d < 32; d++) {
            float4 qv = *(const float4*)&qsT[d][ty * 4];
            ulonglong2 ka = *(const ulonglong2*)&ksT[d][tx * 4];
            ulonglong2 kb2 = *(const ulonglong2*)&ksT[d][tx * 4 + 32];
            ull qa2[4] = {pack2(qv.x, qv.x), pack2(qv.y, qv.y),
                          pack2(qv.z, qv.z), pack2(qv.w, qv.w)};
            #pragma unroll
            for (int qi = 0; qi < 4; qi++) {
                acc2[qi][0] = ffma2(qa2[qi], ka.x, acc2[qi][0]);
                acc2[qi][1] = ffma2(qa2[qi], ka.y, acc2[qi][1]);
                acc2[qi][2] = ffma2(qa2[qi], kb2.x, acc2[qi][2]);
                acc2[qi][3] = ffma2(qa2[qi], kb2.y, acc2[qi][3]);
            }
        }

        #pragma unroll
        for (int qi = 0; qi < 4; qi++) {
            int q = q0 + ty * 4 + qi;
            float2 a0 = unpack2(acc2[qi][0]);
            float2 a1 = unpack2(acc2[qi][1]);
            float2 a2v = unpack2(acc2[qi][2]);
            float2 a3 = unpack2(acc2[qi][3]);
            const int* mp = &mbase[(size_t)q * S + kb];
            int4 m0 = *(const int4*)&mp[tx * 4];
            int4 m1 = *(const int4*)&mp[tx * 4 + 32];
            float4 e0, e1;
            e0.x = m0.x ? fast_exp2(a0.x) : 0.f;
            e0.y = m0.y ? fast_exp2(a0.y) : 0.f;
            e0.z = m0.z ? fast_exp2(a1.x) : 0.f;
            e0.w = m0.w ? fast_exp2(a1.y) : 0.f;
            e1.x = m1.x ? fast_exp2(a2v.x) : 0.f;
            e1.y = m1.y ? fast_exp2(a2v.y) : 0.f;
            e1.z = m1.z ? fast_exp2(a3.x) : 0.f;
            e1.w = m1.w ? fast_exp2(a3.y) : 0.f;
            float* ap = &attno[((size_t)bh * S + q) * S + kb];
            *(float4*)&ap[tx * 4] = e0;
            *(float4*)&ap[tx * 4 + 32] = e1;
            rowacc[qi] += ((e0.x + e0.y) + (e0.z + e0.w)) + ((e1.x + e1.y) + (e1.z + e1.w));
        }
        __syncthreads();
    }

    #pragma unroll
    for (int qi = 0; qi < 4; qi++) {
        float s = rowacc[qi];
        s += __shfl_xor_sync(0xffffffff, s, 4);
        s += __shfl_xor_sync(0xffffffff, s, 2);
        s += __shfl_xor_sync(0xffffffff, s, 1);
        if ((t & 7) == 0) g_rsum[sp * NBH * S + bh * S + q0 + ty * 4 + qi] = s;
    }
}

// ---------------------------------------------------------------------------
// Kernel 4: normalize attno in place, PV GEMM on (p*bias), split-K=4.
// ---------------------------------------------------------------------------
__global__ void __launch_bounds__(128, 8) pv_kernel(float* __restrict__ attno) {
    __shared__ float ps[64][68];    // [q][k]
    __shared__ float vsT[32][68];   // [d][k]
    __shared__ float rinv_s[64];
    int bh = blockIdx.y;
    int h = bh & 7;
    int q0 = blockIdx.x * 64;
    int sp = blockIdx.z;
    int t = threadIdx.x;
    int tx = t & 7;       // d = tx + 8*di
    int tq = t >> 3;      // 0..15, q = tq + 16*qi

    if (t < 64) {
        int i = bh * S + q0 + t;
        float s = g_rsum[i] + g_rsum[NBH * S + i]
                + g_rsum[2 * NBH * S + i] + g_rsum[3 * NBH * S + i];
        rinv_s[t] = 1.0f / s;
    }
    __syncthreads();

    ull acc2[4][4];
    #pragma unroll
    for (int i = 0; i < 4; i++)
        #pragma unroll
        for (int j = 0; j < 4; j++) acc2[i][j] = 0ull;

    const float* biasb = g_bias + ((size_t)h * S + q0) * S;
    float* ab = attno + ((size_t)bh * S + q0) * S;

    for (int kt = sp * 8; kt < sp * 8 + 8; kt++) {
        int kb = kt * 64;
        for (int i = t; i < 512; i += 128) {
            int r = i >> 4, c4 = (i & 15) * 4;
            *(float4*)&vsT[r][c4] = *(const float4*)&g_vhT[((size_t)bh * DK + r) * S + kb + c4];
        }
        for (int i = t; i < 1024; i += 128) {
            int row = i >> 4, c4 = (i & 15) * 4;
            float4 e = *(const float4*)&ab[(size_t)row * S + kb + c4];
            float4 bb = *(const float4*)&biasb[(size_t)row * S + kb + c4];
            float r = rinv_s[row];
            e.x *= r; e.y *= r; e.z *= r; e.w *= r;
            *(float4*)&ab[(size_t)row * S + kb + c4] = e;   // final normalized attno
            *(float4*)&ps[row][c4] = make_float4(e.x * bb.x, e.y * bb.y,
                                                 e.z * bb.z, e.w * bb.w);
        }
        __syncthreads();

        for (int kc = 0; kc < 64; kc += 4) {
            ulonglong2 v2[4];
            #pragma unroll
            for (int di = 0; di < 4; di++)
                v2[di] = *(const ulonglong2*)&vsT[tx + 8 * di][kc];
            #pragma unroll
            for (int qi = 0; qi < 4; qi++) {
                ulonglong2 p2 = *(const ulonglong2*)&ps[tq + 16 * qi][kc];
                #pragma unroll
                for (int di = 0; di < 4; di++) {
                    acc2[qi][di] = ffma2(p2.x, v2[di].x, acc2[qi][di]);
                    acc2[qi][di] = ffma2(p2.y, v2[di].y, acc2[qi][di]);
                }
            }
        }
        __syncthreads();
    }

    float* pout = g_part + (size_t)sp * NBH * S * DK;
    #pragma unroll
    for (int qi = 0; qi < 4; qi++) {
        int q = q0 + tq + 16 * qi;
        #pragma unroll
        for (int di = 0; di < 4; di++) {
            float2 v = unpack2(acc2[qi][di]);
            pout[((size_t)bh * S + q) * DK + tx + 8 * di] = v.x + v.y;
        }
    }
}

// ---------------------------------------------------------------------------
// Kernel 4b: reduce PVSPLIT partials into g_ctx [m][d] layout.
// ---------------------------------------------------------------------------
__global__ void pv_reduce_kernel() {
    int idx = blockIdx.x * 256 + threadIdx.x;
    int flat = idx * 4;
    float4 a = *(const float4*)&g_part[flat];
    #pragma unroll
    for (int sp = 1; sp < PVSPLIT; sp++) {
        float4 c = *(const float4*)&g_part[(size_t)sp * NBH * S * DK + flat];
        a.x += c.x; a.y += c.y; a.z += c.z; a.w += c.w;
    }
    int bh = flat >> 16;
    int rem = flat & 65535;
    int q = rem >> 5, dk = rem & 31;
    int b = bh >> 3, h = bh & 7;
    *(float4*)&g_ctx[((size_t)(q * B + b)) * D + h * DK + dk] = a;
}

// ---------------------------------------------------------------------------
// Kernel 5: fc GEMM + residual, FFMA2 inner loop.
// ---------------------------------------------------------------------------
__global__ void fc_kernel(const float* __restrict__ resid, const float* __restrict__ wfc) {
    __shared__ float asT[16][68];
    __shared__ float bs[16][68];
    int m0 = blockIdx.x * 64, n0 = blockIdx.y * 64;
    int t = threadIdx.x;
    int tx = t & 15, ty = t >> 4;
    int lrowA = t >> 2, lkA = (t & 3) * 4;
    int lkB = t >> 4, lnB = (t & 15) * 4;

    ull acc2[4][2];
    #pragma unroll
    for (int i = 0; i < 4; i++) { acc2[i][0] = 0ull; acc2[i][1] = 0ull; }

    for (int k0 = 0; k0 < D; k0 += 16) {
        float4 a4 = *(const float4*)&g_ctx[(size_t)(m0 + lrowA) * D + k0 + lkA];
        float4 b4 = *(const float4*)&wfc[(size_t)(k0 + lkB) * D + n0 + lnB];
        asT[lkA + 0][lrowA] = a4.x; asT[lkA + 1][lrowA] = a4.y;
        asT[lkA + 2][lrowA] = a4.z; asT[lkA + 3][lrowA] = a4.w;
        *(float4*)&bs[lkB][lnB] = b4;
        __syncthreads();
        #pragma unroll
        for (int kk = 0; kk < 16; kk++) {
            float4 av = *(const float4*)&asT[kk][ty * 4];
            const ull* bp = (const ull*)&bs[kk][tx * 4];
            ull b0 = bp[0], b1 = bp[1];
            ull a2[4] = {pack2(av.x, av.x), pack2(av.y, av.y),
                         pack2(av.z, av.z), pack2(av.w, av.w)};
            #pragma unroll
            for (int i = 0; i < 4; i++) {
                acc2[i][0] = ffma2(a2[i], b0, acc2[i][0]);
                acc2[i][1] = ffma2(a2[i], b1, acc2[i][1]);
            }
        }
        __syncthreads();
    }
    #pragma unroll
    for (int qi = 0; qi < 4; qi++) {
        int m = m0 + ty * 4 + qi;
        int n = n0 + tx * 4;
        float4 r4 = *(const float4*)&resid[(size_t)m * D + n];
        float2 lo = unpack2(acc2[qi][0]);
        float2 hi = unpack2(acc2[qi][1]);
        float4 o = make_float4(lo.x + r4.x, lo.y + r4.y, hi.x + r4.z, hi.y + r4.w);
        *(float4*)&g_fc[(size_t)m * D + n] = o;
    }
}

// ---------------------------------------------------------------------------
// Kernel 6: LayerNorm, warp per row.
// ---------------------------------------------------------------------------
__global__ void ln_kernel(const float* __restrict__ gamma, const float* __restrict__ beta,
                          float* __restrict__ out) {
    int m = blockIdx.x * 8 + (threadIdx.x >> 5);
    int lane = threadIdx.x & 31;
    const float* row = g_fc + (size_t)m * D;
    float4 v0 = *(const float4*)&row[lane * 4];
    float4 v1 = *(const float4*)&row[128 + lane * 4];
    float s1 = v0.x + v0.y + v0.z + v0.w + v1.x + v1.y + v1.z + v1.w;
    float s2 = v0.x * v0.x + v0.y * v0.y + v0.z * v0.z + v0.w * v0.w
             + v1.x * v1.x + v1.y * v1.y + v1.z * v1.z + v1.w * v1.w;
    #pragma unroll
    for (int o = 16; o > 0; o >>= 1) {
        s1 += __shfl_xor_sync(0xffffffff, s1, o);
        s2 += __shfl_xor_sync(0xffffffff, s2, o);
    }
    float mu = s1 * (1.0f / 256.0f);
    float var = s2 * (1.0f / 256.0f) - mu * mu;
    float rstd = rsqrtf(var + 1e-6f);
    float4 g0 = *(const float4*)&gamma[lane * 4];
    float4 g1 = *(const float4*)&gamma[128 + lane * 4];
    float4 b0 = *(const float4*)&beta[lane * 4];
    float4 b1 = *(const float4*)&beta[128 + lane * 4];
    float4 o0 = make_float4((v0.x - mu) * rstd * g0.x + b0.x,
                            (v0.y - mu) * rstd * g0.y + b0.y,
                            (v0.z - mu) * rstd * g0.z + b0.z,
                            (v0.w - mu) * rstd * g0.w + b0.w);
    float4 o1 = make_float4((v1.x - mu) * rstd * g1.x + b1.x,
                            (v1.y - mu) * rstd * g1.y + b1.y,
                            (v1.z - mu) * rstd * g1.z + b1.z,
                            (v1.w - mu) * rstd * g1.w + b1.w);
    *(float4*)&out[(size_t)m * D + lane * 4] = o0;
    *(float4*)&out[(size_t)m * D + 128 + lane * 4] = o1;
}

extern "C" void kernel_launch(void* const* d_in, const int* in_sizes, int n_in,
                              void* d_out, int out_size) {
    const float* q     = (const float*)d_in[0];
    const float* k     = (const float*)d_in[1];
    const float* v     = (const float*)d_in[2];
    const float* gp    = (const float*)d_in[3];
    const int*   mask  = (const int*)d_in[4];
    const float* wq    = (const float*)d_in[5];
    const float* wk    = (const float*)d_in[6];
    const float* wv    = (const float*)d_in[7];
    const float* wfc   = (const float*)d_in[8];
    const float* gamma = (const float*)d_in[9];
    const float* beta  = (const float*)d_in[10];

    float* out = (float*)d_out;
    float* attno = out + (size_t)S * B * D;

    proj_kernel<<<dim3(S * B / 64, D / 64, 3), 256>>>(q, k, v, wq, wk, wv);
    head_transpose_kernel<<<dim3(S / 64, NBH, 3), 128>>>();
    // z in [0,SPLIT): qk compute; z in [SPLIT, SPLIT+64): bias transpose blocks
    qk_bias_kernel<<<dim3(S / 64, NBH, SPLIT + 64), 128>>>(mask, attno, gp);
    pv_kernel<<<dim3(S / 64, NBH, PVSPLIT), 128>>>(attno);
    pv_reduce_kernel<<<NBH * S * DK / 4 / 256, 256>>>();
    fc_kernel<<<dim3(S * B / 64, D / 64), 256>>>(q, wfc);
    ln_kernel<<<S * B / 8, 256>>>(gamma, beta, out);
}

// round 13
// speedup vs baseline: 1.2035x; 1.0732x over previous
#include <cuda_runtime.h>
#include <math.h>

#define S 2048
#define B 2
#define D 256
#define H 8
#define DK 32
#define NBH 16
#define SPLIT 4
#define PVSPLIT 4
// fold log2(e)/sqrt(DK) into Q at projection time; then exp(s) == exp2(acc)
#define QSCALE (1.4426950408889634f * 0.17677669529663687f)

typedef unsigned long long ull;

__device__ float g_qh[NBH * S * DK];        // [bh, s, dk]
__device__ float g_kh[NBH * S * DK];
__device__ float g_vh[NBH * S * DK];
__device__ float g_qhT[NBH * DK * S];       // [bh, dk, s]
__device__ float g_khT[NBH * DK * S];
__device__ float g_vhT[NBH * DK * S];
__device__ float g_bias[(size_t)H * S * S]; // [h, q, k]
__device__ float g_rsum[SPLIT * NBH * S];   // partial rowsums from qk
__device__ float g_part[PVSPLIT * NBH * S * DK]; // pv split-k partials
__device__ float g_ctx[S * B * D];          // [m = s*B+b, d]
__device__ float g_fc[S * B * D];           // fc output + residual

__device__ __forceinline__ float fast_exp2(float x) {
    float r;
    asm("ex2.approx.f32 %0, %1;" : "=f"(r) : "f"(x));
    return r;
}
// packed fp32x2 FMA (Blackwell): d = a*b + c lanewise, rn rounding (== fmaf)
__device__ __forceinline__ ull ffma2(ull a, ull b, ull c) {
    ull d;
    asm("fma.rn.f32x2 %0, %1, %2, %3;" : "=l"(d) : "l"(a), "l"(b), "l"(c));
    return d;
}
__device__ __forceinline__ ull pack2(float x, float y) {
    ull r;
    asm("mov.b64 %0, {%1, %2};" : "=l"(r) : "f"(x), "f"(y));
    return r;
}
__device__ __forceinline__ float2 unpack2(ull v) {
    float2 r;
    asm("mov.b64 {%0, %1}, %2;" : "=f"(r.x), "=f"(r.y) : "l"(v));
    return r;
}

// ---------------------------------------------------------------------------
// Kernel 1: QKV projections. 64x64 tile SGEMM, 256 threads, 4x4 micro-tile.
// ---------------------------------------------------------------------------
__global__ void proj_kernel(const float* __restrict__ q, const float* __restrict__ k,
                            const float* __restrict__ v,
                            const float* __restrict__ wq, const float* __restrict__ wk,
                            const float* __restrict__ wv) {
    __shared__ float asT[16][68];  // [k][m]
    __shared__ float bs[16][68];   // [k][n]
    int which = blockIdx.z;
    const float* x = (which == 0) ? q : (which == 1 ? k : v);
    const float* w = (which == 0) ? wq : (which == 1 ? wk : wv);
    float* out = (which == 0) ? g_qh : (which == 1 ? g_kh : g_vh);

    int m0 = blockIdx.x * 64, n0 = blockIdx.y * 64;
    int t = threadIdx.x;
    int tx = t & 15, ty = t >> 4;
    int lrowA = t >> 2, lkA = (t & 3) * 4;
    int lkB = t >> 4, lnB = (t & 15) * 4;

    ull acc2[4][2];
    #pragma unroll
    for (int i = 0; i < 4; i++) { acc2[i][0] = 0ull; acc2[i][1] = 0ull; }

    for (int k0 = 0; k0 < D; k0 += 16) {
        float4 a4 = *(const float4*)&x[(size_t)(m0 + lrowA) * D + k0 + lkA];
        float4 b4 = *(const float4*)&w[(size_t)(k0 + lkB) * D + n0 + lnB];
        asT[lkA + 0][lrowA] = a4.x; asT[lkA + 1][lrowA] = a4.y;
        asT[lkA + 2][lrowA] = a4.z; asT[lkA + 3][lrowA] = a4.w;
        *(float4*)&bs[lkB][lnB] = b4;
        __syncthreads();
        #pragma unroll
        for (int kk = 0; kk < 16; kk++) {
            float4 av = *(const float4*)&asT[kk][ty * 4];
            const ull* bp = (const ull*)&bs[kk][tx * 4];
            ull b0 = bp[0], b1 = bp[1];
            ull a2[4] = {pack2(av.x, av.x), pack2(av.y, av.y),
                         pack2(av.z, av.z), pack2(av.w, av.w)};
            #pragma unroll
            for (int i = 0; i < 4; i++) {
                acc2[i][0] = ffma2(a2[i], b0, acc2[i][0]);
                acc2[i][1] = ffma2(a2[i], b1, acc2[i][1]);
            }
        }
        __syncthreads();
    }
    float sc = (which == 0) ? QSCALE : 1.0f;
    int n = n0 + tx * 4;
    int h = n >> 5, dk = n & 31;
    #pragma unroll
    for (int qi = 0; qi < 4; qi++) {
        int m = m0 + ty * 4 + qi;
        int b = m & 1, s = m >> 1;
        float2 lo = unpack2(acc2[qi][0]);
        float2 hi = unpack2(acc2[qi][1]);
        float4 o = make_float4(lo.x * sc, lo.y * sc, hi.x * sc, hi.y * sc);
        *(float4*)&out[((size_t)(b * H + h) * S + s) * DK + dk] = o;
    }
}

// ---------------------------------------------------------------------------
// Kernel 1b: transpose heads [bh, s, dk] -> [bh, dk, s] for Q, K, V.
// ---------------------------------------------------------------------------
__global__ void head_transpose_kernel() {
    __shared__ float ts[64][33];
    int z = blockIdx.z;
    const float* src = (z == 0) ? g_qh : (z == 1 ? g_kh : g_vh);
    float* dst = (z == 0) ? g_qhT : (z == 1 ? g_khT : g_vhT);
    int bh = blockIdx.y;
    int s0 = blockIdx.x * 64;
    int t = threadIdx.x;

    for (int i = t; i < 512; i += 128) {
        int r = i >> 3, d4 = (i & 7) * 4;
        float4 a = *(const float4*)&src[((size_t)bh * S + s0 + r) * DK + d4];
        ts[r][d4 + 0] = a.x; ts[r][d4 + 1] = a.y;
        ts[r][d4 + 2] = a.z; ts[r][d4 + 3] = a.w;
    }
    __syncthreads();

    int d = t >> 2, c = t & 3;
    #pragma unroll
    for (int iter = 0; iter < 4; iter++) {
        int sl = c * 4 + iter * 16;
        float4 o = make_float4(ts[sl + 0][d], ts[sl + 1][d], ts[sl + 2][d], ts[sl + 3][d]);
        *(float4*)&dst[((size_t)bh * DK + d) * S + s0 + sl] = o;
    }
}

// ---------------------------------------------------------------------------
// Kernel 2: transpose graph_pos [k,q,h] -> g_bias [h,q,k].
// ---------------------------------------------------------------------------
__global__ void bias_transpose_kernel(const float* __restrict__ gp) {
    int qrow = blockIdx.y;
    int kk = blockIdx.x * 256 + threadIdx.x;
    const float4* p = reinterpret_cast<const float4*>(gp + ((size_t)kk * S + qrow) * H);
    float4 a = p[0];
    float4 b4 = p[1];
    float vals[8] = {a.x, a.y, a.z, a.w, b4.x, b4.y, b4.z, b4.w};
    #pragma unroll
    for (int h = 0; h < 8; h++)
        g_bias[((size_t)h * S + qrow) * S + kk] = vals[h];
}

// ---------------------------------------------------------------------------
// Kernel 3: QK + exp + mask, split-K=4. Conflict-free LDS.128, FFMA2 pairs.
// (round-9 version, measured 119us)
// ---------------------------------------------------------------------------
__global__ void __launch_bounds__(128) qk_kernel(const int* __restrict__ mask,
                                                 float* __restrict__ attno) {
    __shared__ float qsT[32][68];  // [d][q]
    __shared__ float ksT[32][68];  // [d][k]
    int bh = blockIdx.y;
    int b = bh >> 3;
    int q0 = blockIdx.x * 64;
    int sp = blockIdx.z;
    int t = threadIdx.x;
    int tx = t & 7, ty = t >> 3;   // tx: k columns, ty: 4q rows

    for (int i = t; i < 512; i += 128) {
        int r = i >> 4, c4 = (i & 15) * 4;
        *(float4*)&qsT[r][c4] = *(const float4*)&g_qhT[((size_t)bh * DK + r) * S + q0 + c4];
    }

    float rowacc[4] = {0.f, 0.f, 0.f, 0.f};
    const int* mbase = mask + (size_t)b * S * S;

    for (int kt = sp * 8; kt < sp * 8 + 8; kt++) {
        int kb = kt * 64;
        for (int i = t; i < 512; i += 128) {
            int r = i >> 4, c4 = (i & 15) * 4;
            *(float4*)&ksT[r][c4] = *(const float4*)&g_khT[((size_t)bh * DK + r) * S + kb + c4];
        }
        __syncthreads();

        ull acc2[4][4];
        #pragma unroll
        for (int i = 0; i < 4; i++)
            #pragma unroll
            for (int j = 0; j < 4; j++) acc2[i][j] = 0ull;

        #pragma unroll 8
        for (int d = 0; d < 32; d++) {
            float4 qv = *(const float4*)&qsT[d][ty * 4];
            ulonglong2 ka = *(const ulonglong2*)&ksT[d][tx * 4];
            ulonglong2 kb2 = *(const ulonglong2*)&ksT[d][tx * 4 + 32];
            ull qa2[4] = {pack2(qv.x, qv.x), pack2(qv.y, qv.y),
                          pack2(qv.z, qv.z), pack2(qv.w, qv.w)};
            #pragma unroll
            for (int qi = 0; qi < 4; qi++) {
                acc2[qi][0] = ffma2(qa2[qi], ka.x, acc2[qi][0]);
                acc2[qi][1] = ffma2(qa2[qi], ka.y, acc2[qi][1]);
                acc2[qi][2] = ffma2(qa2[qi], kb2.x, acc2[qi][2]);
                acc2[qi][3] = ffma2(qa2[qi], kb2.y, acc2[qi][3]);
            }
        }

        #pragma unroll
        for (int qi = 0; qi < 4; qi++) {
            int q = q0 + ty * 4 + qi;
            float2 a0 = unpack2(acc2[qi][0]);
            float2 a1 = unpack2(acc2[qi][1]);
            float2 a2v = unpack2(acc2[qi][2]);
            float2 a3 = unpack2(acc2[qi][3]);
            const int* mp = &mbase[(size_t)q * S + kb];
            int4 m0 = *(const int4*)&mp[tx * 4];
            int4 m1 = *(const int4*)&mp[tx * 4 + 32];
            float4 e0, e1;
            e0.x = m0.x ? fast_exp2(a0.x) : 0.f;
            e0.y = m0.y ? fast_exp2(a0.y) : 0.f;
            e0.z = m0.z ? fast_exp2(a1.x) : 0.f;
            e0.w = m0.w ? fast_exp2(a1.y) : 0.f;
            e1.x = m1.x ? fast_exp2(a2v.x) : 0.f;
            e1.y = m1.y ? fast_exp2(a2v.y) : 0.f;
            e1.z = m1.z ? fast_exp2(a3.x) : 0.f;
            e1.w = m1.w ? fast_exp2(a3.y) : 0.f;
            float* ap = &attno[((size_t)bh * S + q) * S + kb];
            *(float4*)&ap[tx * 4] = e0;
            *(float4*)&ap[tx * 4 + 32] = e1;
            rowacc[qi] += ((e0.x + e0.y) + (e0.z + e0.w)) + ((e1.x + e1.y) + (e1.z + e1.w));
        }
        __syncthreads();
    }

    #pragma unroll
    for (int qi = 0; qi < 4; qi++) {
        float s = rowacc[qi];
        s += __shfl_xor_sync(0xffffffff, s, 4);
        s += __shfl_xor_sync(0xffffffff, s, 2);
        s += __shfl_xor_sync(0xffffffff, s, 1);
        if ((t & 7) == 0) g_rsum[sp * NBH * S + bh * S + q0 + ty * 4 + qi] = s;
    }
}

// ---------------------------------------------------------------------------
// Kernel 4: normalize attno in place, PV GEMM on (p*bias), split-K=4.
// 256 threads, micro 4q x 2d, acc 16 regs -> launch_bounds(256,5): 40 warps/SM.
// tx = t&15 (d = tx, tx+16), tq = t>>4 (q = tq + 16*qi).
// vsT reads: quarter-warp phases see 8 consecutive rows, pitch 68 ->
// bank starts 4r mod 32 distinct per phase (conflict-free).
// ---------------------------------------------------------------------------
__global__ void __launch_bounds__(256, 5) pv_kernel(float* __restrict__ attno) {
    __shared__ float ps[64][68];    // [q][k]
    __shared__ float vsT[32][68];   // [d][k]
    __shared__ float rinv_s[64];
    int bh = blockIdx.y;
    int h = bh & 7;
    int q0 = blockIdx.x * 64;
    int sp = blockIdx.z;
    int t = threadIdx.x;
    int tx = t & 15;      // d = tx + 16*di, di in {0,1}
    int tq = t >> 4;      // 0..15, q = tq + 16*qi

    if (t < 64) {
        int i = bh * S + q0 + t;
        float s = g_rsum[i] + g_rsum[NBH * S + i]
                + g_rsum[2 * NBH * S + i] + g_rsum[3 * NBH * S + i];
        rinv_s[t] = 1.0f / s;
    }
    __syncthreads();

    ull acc2[4][2];
    #pragma unroll
    for (int i = 0; i < 4; i++) { acc2[i][0] = 0ull; acc2[i][1] = 0ull; }

    const float* biasb = g_bias + ((size_t)h * S + q0) * S;
    float* ab = attno + ((size_t)bh * S + q0) * S;

    for (int kt = sp * 8; kt < sp * 8 + 8; kt++) {
        int kb = kt * 64;
        // V tile [d][k] from transposed layout: 512 f4 / 256 thr = 2 iters
        for (int i = t; i < 512; i += 256) {
            int r = i >> 4, c4 = (i & 15) * 4;
            *(float4*)&vsT[r][c4] = *(const float4*)&g_vhT[((size_t)bh * DK + r) * S + kb + c4];
        }
        // attno normalize + writeback + ps = p*bias: 1024 f4 / 256 thr = 4 iters
        for (int i = t; i < 1024; i += 256) {
            int row = i >> 4, c4 = (i & 15) * 4;
            float4 e = *(const float4*)&ab[(size_t)row * S + kb + c4];
            float4 bb = *(const float4*)&biasb[(size_t)row * S + kb + c4];
            float r = rinv_s[row];
            e.x *= r; e.y *= r; e.z *= r; e.w *= r;
            *(float4*)&ab[(size_t)row * S + kb + c4] = e;   // final normalized attno
            *(float4*)&ps[row][c4] = make_float4(e.x * bb.x, e.y * bb.y,
                                                 e.z * bb.z, e.w * bb.w);
        }
        __syncthreads();

        for (int kc = 0; kc < 64; kc += 4) {
            ulonglong2 v0 = *(const ulonglong2*)&vsT[tx][kc];
            ulonglong2 v1 = *(const ulonglong2*)&vsT[tx + 16][kc];
            #pragma unroll
            for (int qi = 0; qi < 4; qi++) {
                ulonglong2 p2 = *(const ulonglong2*)&ps[tq + 16 * qi][kc];
                acc2[qi][0] = ffma2(p2.x, v0.x, acc2[qi][0]);
                acc2[qi][0] = ffma2(p2.y, v0.y, acc2[qi][0]);
                acc2[qi][1] = ffma2(p2.x, v1.x, acc2[qi][1]);
                acc2[qi][1] = ffma2(p2.y, v1.y, acc2[qi][1]);
            }
        }
        __syncthreads();
    }

    float* pout = g_part + (size_t)sp * NBH * S * DK;
    #pragma unroll
    for (int qi = 0; qi < 4; qi++) {
        int q = q0 + tq + 16 * qi;
        float2 v0 = unpack2(acc2[qi][0]);
        float2 v1 = unpack2(acc2[qi][1]);
        pout[((size_t)bh * S + q) * DK + tx]      = v0.x + v0.y;
        pout[((size_t)bh * S + q) * DK + tx + 16] = v1.x + v1.y;
    }
}

// ---------------------------------------------------------------------------
// Kernel 4b: reduce PVSPLIT partials into g_ctx [m][d] layout.
// ---------------------------------------------------------------------------
__global__ void pv_reduce_kernel() {
    int idx = blockIdx.x * 256 + threadIdx.x;
    int flat = idx * 4;
    float4 a = *(const float4*)&g_part[flat];
    #pragma unroll
    for (int sp = 1; sp < PVSPLIT; sp++) {
        float4 c = *(const float4*)&g_part[(size_t)sp * NBH * S * DK + flat];
        a.x += c.x; a.y += c.y; a.z += c.z; a.w += c.w;
    }
    int bh = flat >> 16;
    int rem = flat & 65535;
    int q = rem >> 5, dk = rem & 31;
    int b = bh >> 3, h = bh & 7;
    *(float4*)&g_ctx[((size_t)(q * B + b)) * D + h * DK + dk] = a;
}

// ---------------------------------------------------------------------------
// Kernel 5: fc GEMM + residual, FFMA2 inner loop.
// ---------------------------------------------------------------------------
__global__ void fc_kernel(const float* __restrict__ resid, const float* __restrict__ wfc) {
    __shared__ float asT[16][68];
    __shared__ float bs[16][68];
    int m0 = blockIdx.x * 64, n0 = blockIdx.y * 64;
    int t = threadIdx.x;
    int tx = t & 15, ty = t >> 4;
    int lrowA = t >> 2, lkA = (t & 3) * 4;
    int lkB = t >> 4, lnB = (t & 15) * 4;

    ull acc2[4][2];
    #pragma unroll
    for (int i = 0; i < 4; i++) { acc2[i][0] = 0ull; acc2[i][1] = 0ull; }

    for (int k0 = 0; k0 < D; k0 += 16) {
        float4 a4 = *(const float4*)&g_ctx[(size_t)(m0 + lrowA) * D + k0 + lkA];
        float4 b4 = *(const float4*)&wfc[(size_t)(k0 + lkB) * D + n0 + lnB];
        asT[lkA + 0][lrowA] = a4.x; asT[lkA + 1][lrowA] = a4.y;
        asT[lkA + 2][lrowA] = a4.z; asT[lkA + 3][lrowA] = a4.w;
        *(float4*)&bs[lkB][lnB] = b4;
        __syncthreads();
        #pragma unroll
        for (int kk = 0; kk < 16; kk++) {
            float4 av = *(const float4*)&asT[kk][ty * 4];
            const ull* bp = (const ull*)&bs[kk][tx * 4];
            ull b0 = bp[0], b1 = bp[1];
            ull a2[4] = {pack2(av.x, av.x), pack2(av.y, av.y),
                         pack2(av.z, av.z), pack2(av.w, av.w)};
            #pragma unroll
            for (int i = 0; i < 4; i++) {
                acc2[i][0] = ffma2(a2[i], b0, acc2[i][0]);
                acc2[i][1] = ffma2(a2[i], b1, acc2[i][1]);
            }
        }
        __syncthreads();
    }
    #pragma unroll
    for (int qi = 0; qi < 4; qi++) {
        int m = m0 + ty * 4 + qi;
        int n = n0 + tx * 4;
        float4 r4 = *(const float4*)&resid[(size_t)m * D + n];
        float2 lo = unpack2(acc2[qi][0]);
        float2 hi = unpack2(acc2[qi][1]);
        float4 o = make_float4(lo.x + r4.x, lo.y + r4.y, hi.x + r4.z, hi.y + r4.w);
        *(float4*)&g_fc[(size_t)m * D + n] = o;
    }
}

// ---------------------------------------------------------------------------
// Kernel 6: LayerNorm, warp per row.
// ---------------------------------------------------------------------------
__global__ void ln_kernel(const float* __restrict__ gamma, const float* __restrict__ beta,
                          float* __restrict__ out) {
    int m = blockIdx.x * 8 + (threadIdx.x >> 5);
    int lane = threadIdx.x & 31;
    const float* row = g_fc + (size_t)m * D;
    float4 v0 = *(const float4*)&row[lane * 4];
    float4 v1 = *(const float4*)&row[128 + lane * 4];
    float s1 = v0.x + v0.y + v0.z + v0.w + v1.x + v1.y + v1.z + v1.w;
    float s2 = v0.x * v0.x + v0.y * v0.y + v0.z * v0.z + v0.w * v0.w
             + v1.x * v1.x + v1.y * v1.y + v1.z * v1.z + v1.w * v1.w;
    #pragma unroll
    for (int o = 16; o > 0; o >>= 1) {
        s1 += __shfl_xor_sync(0xffffffff, s1, o);
        s2 += __shfl_xor_sync(0xffffffff, s2, o);
    }
    float mu = s1 * (1.0f / 256.0f);
    float var = s2 * (1.0f / 256.0f) - mu * mu;
    float rstd = rsqrtf(var + 1e-6f);
    float4 g0 = *(const float4*)&gamma[lane * 4];
    float4 g1 = *(const float4*)&gamma[128 + lane * 4];
    float4 b0 = *(const float4*)&beta[lane * 4];
    float4 b1 = *(const float4*)&beta[128 + lane * 4];
    float4 o0 = make_float4((v0.x - mu) * rstd * g0.x + b0.x,
                            (v0.y - mu) * rstd * g0.y + b0.y,
                            (v0.z - mu) * rstd * g0.z + b0.z,
                            (v0.w - mu) * rstd * g0.w + b0.w);
    float4 o1 = make_float4((v1.x - mu) * rstd * g1.x + b1.x,
                            (v1.y - mu) * rstd * g1.y + b1.y,
                            (v1.z - mu) * rstd * g1.z + b1.z,
                            (v1.w - mu) * rstd * g1.w + b1.w);
    *(float4*)&out[(size_t)m * D + lane * 4] = o0;
    *(float4*)&out[(size_t)m * D + 128 + lane * 4] = o1;
}

extern "C" void kernel_launch(void* const* d_in, const int* in_sizes, int n_in,
                              void* d_out, int out_size) {
    const float* q     = (const float*)d_in[0];
    const float* k     = (const float*)d_in[1];
    const float* v     = (const float*)d_in[2];
    const float* gp    = (const float*)d_in[3];
    const int*   mask  = (const int*)d_in[4];
    const float* wq    = (const float*)d_in[5];
    const float* wk    = (const float*)d_in[6];
    const float* wv    = (const float*)d_in[7];
    const float* wfc   = (const float*)d_in[8];
    const float* gamma = (const float*)d_in[9];
    const float* beta  = (const float*)d_in[10];

    float* out = (float*)d_out;
    float* attno = out + (size_t)S * B * D;

    bias_transpose_kernel<<<dim3(S / 256, S), 256>>>(gp);
    proj_kernel<<<dim3(S * B / 64, D / 64, 3), 256>>>(q, k, v, wq, wk, wv);
    head_transpose_kernel<<<dim3(S / 64, NBH, 3), 128>>>();
    qk_kernel<<<dim3(S / 64, NBH, SPLIT), 128>>>(mask, attno);
    pv_kernel<<<dim3(S / 64, NBH, PVSPLIT), 256>>>(attno);
    pv_reduce_kernel<<<NBH * S * DK / 4 / 256, 256>>>();
    fc_kernel<<<dim3(S * B / 64, D / 64), 256>>>(q, wfc);
    ln_kernel<<<S * B / 8, 256>>>(gamma, beta, out);
}